// round 17
// baseline (speedup 1.0000x reference)
#include <cuda_runtime.h>
#include <cuda_fp16.h>
#include <math.h>

typedef unsigned int       u32;
typedef unsigned short     u16;
typedef unsigned long long u64;

#define BATCH 8
#define CIN   64
#define COUT  128
#define HH    128
#define WW    128

// ---------------- device globals ----------------
// Even/odd split constant matrices, fp16 hi/lo planes, packed [row][col/2] u32 (64x32).
__device__ u32 g_Deh[2048], g_Del[2048];   // De[k'][h'] = D[2k'][h']
__device__ u32 g_Doh[2048], g_Dol[2048];   // Do[k'][h'] = D[2k'+1][h']
__device__ u32 g_Meh[2048], g_Mel[2048];   // Me[n'][k'] = 256*M[n'][2k']
__device__ u32 g_Moh[2048], g_Mol[2048];   // Mo[n'][k'] = 256*M[n'][2k'+1]
__device__ float g_D5[640];                // first 5 cols of D (fp32, for wtrans)
__device__ u32 g_wdh[128*5*4096], g_wdl[128*5*4096];   // x64 [k][j] tiles of [o][c/2]
__device__ u32 g_xd16[BATCH*CIN*HH*64];    // [b][c][k][w/2] single fp16 plane
__device__ u32 g_y16 [BATCH*COUT*HH*64];   // [b][o][k][w/2]

// ---------------- helpers ----------------
__device__ __forceinline__ u32 smem_u32(const void* p) {
    u32 a; asm("{ .reg .u64 t; cvta.to.shared.u64 t, %1; cvt.u32.u64 %0, t; }" : "=r"(a) : "l"(p));
    return a;
}
__device__ __forceinline__ void cp16(u32 dst, const void* src) {
    asm volatile("cp.async.cg.shared.global [%0], [%1], 16;" :: "r"(dst), "l"(src) : "memory");
}
#define CP_COMMIT() asm volatile("cp.async.commit_group;" ::: "memory")
#define CP_WAIT(n)  asm volatile("cp.async.wait_group %0;" :: "n"(n) : "memory")

__device__ __forceinline__ void ldsm_x4(u32& r0, u32& r1, u32& r2, u32& r3, u32 addr) {
    asm volatile("ldmatrix.sync.aligned.m8n8.x4.shared.b16 {%0,%1,%2,%3}, [%4];"
        : "=r"(r0), "=r"(r1), "=r"(r2), "=r"(r3) : "r"(addr) : "memory");
}
__device__ __forceinline__ void ldsm_x4t(u32& r0, u32& r1, u32& r2, u32& r3, u32 addr) {
    asm volatile("ldmatrix.sync.aligned.m8n8.x4.trans.shared.b16 {%0,%1,%2,%3}, [%4];"
        : "=r"(r0), "=r"(r1), "=r"(r2), "=r"(r3) : "r"(addr) : "memory");
}
__device__ __forceinline__ void mma_f16(float* c, const u32* a, u32 b0, u32 b1) {
    asm volatile("mma.sync.aligned.m16n8k16.row.col.f32.f16.f16.f32 "
        "{%0,%1,%2,%3}, {%4,%5,%6,%7}, {%8,%9}, {%0,%1,%2,%3};"
        : "+f"(c[0]), "+f"(c[1]), "+f"(c[2]), "+f"(c[3])
        : "r"(a[0]), "r"(a[1]), "r"(a[2]), "r"(a[3]), "r"(b0), "r"(b1));
}
__device__ __forceinline__ void f2h2(float v, u16& h, u16& l) {
    __half hh = __float2half_rn(v);
    float fh = __half2float(hh);
    __half ll = __float2half_rn(v - fh);
    h = __half_as_ushort(hh);
    l = __half_as_ushort(ll);
}
__device__ __forceinline__ u16 f2h(float v) { return __half_as_ushort(__float2half_rn(v)); }

// ---------------- constants ----------------
__global__ void k_consts() {
    int idx = blockIdx.x * blockDim.x + threadIdx.x;
    if (idx < 640) {
        int k = idx / 5, h = idx % 5;
        g_D5[idx] = (float)(2.0 * cos(M_PI * (2.0*h + 1.0) * k / 256.0));
    }
    if (idx >= 2048) return;
    int r = idx >> 5, cp = idx & 31;
    int c0 = 2*cp, c1 = 2*cp + 1;
    u16 h0, l0, h1, l1;
    float de0 = (float)(2.0 * cos(M_PI * (2.0*c0 + 1.0) * (2.0*r) / 256.0));
    float de1 = (float)(2.0 * cos(M_PI * (2.0*c1 + 1.0) * (2.0*r) / 256.0));
    f2h2(de0, h0, l0); f2h2(de1, h1, l1);
    g_Deh[idx] = (u32)h0 | ((u32)h1 << 16);
    g_Del[idx] = (u32)l0 | ((u32)l1 << 16);
    float do0 = (float)(2.0 * cos(M_PI * (2.0*c0 + 1.0) * (2.0*r + 1.0) / 256.0));
    float do1 = (float)(2.0 * cos(M_PI * (2.0*c1 + 1.0) * (2.0*r + 1.0) / 256.0));
    f2h2(do0, h0, l0); f2h2(do1, h1, l1);
    g_Doh[idx] = (u32)h0 | ((u32)h1 << 16);
    g_Dol[idx] = (u32)l0 | ((u32)l1 << 16);
    float me0 = (float)(cos(M_PI * (2.0*r + 1.0) * (2.0*c0) / 256.0) * ((c0 == 0) ? 0.5 : 1.0));
    float me1 = (float)(cos(M_PI * (2.0*r + 1.0) * (2.0*c1) / 256.0));
    f2h2(me0, h0, l0); f2h2(me1, h1, l1);
    g_Meh[idx] = (u32)h0 | ((u32)h1 << 16);
    g_Mel[idx] = (u32)l0 | ((u32)l1 << 16);
    float mo0 = (float)(cos(M_PI * (2.0*r + 1.0) * (2.0*c0 + 1.0) / 256.0));
    float mo1 = (float)(cos(M_PI * (2.0*r + 1.0) * (2.0*c1 + 1.0) / 256.0));
    f2h2(mo0, h0, l0); f2h2(mo1, h1, l1);
    g_Moh[idx] = (u32)h0 | ((u32)h1 << 16);
    g_Mol[idx] = (u32)l0 | ((u32)l1 << 16);
}

// ---------------- weight transform: wd[k][j][o][c] = 64 * sum_h D[k,h]*W[o,c,h,j] ----------------
__global__ void k_wtrans(const float* __restrict__ wgt) {
    __shared__ float sw[5*64];
    int j = blockIdx.x >> 7, o = blockIdx.x & 127;
    int tid = threadIdx.x;
    for (int i = tid; i < 320; i += 256) {
        int h = i >> 6, c = i & 63;
        sw[h*64 + c] = wgt[((o*64 + c)*5 + h)*5 + j];
    }
    __syncthreads();
    for (int i = tid; i < 4096; i += 256) {
        int k = i >> 5, cp = i & 31;
        float a0 = 0.f, a1 = 0.f;
#pragma unroll
        for (int h = 0; h < 5; h++) {
            float d = g_D5[k*5 + h];
            a0 = fmaf(d, sw[h*64 + 2*cp],     a0);
            a1 = fmaf(d, sw[h*64 + 2*cp + 1], a1);
        }
        u16 h0, l0, h1, l1;
        f2h2(64.f * a0, h0, l0);
        f2h2(64.f * a1, h1, l1);
        u32 oi = (u32)(k*5 + j)*4096 + o*32 + cp;
        g_wdh[oi] = (u32)h0 | ((u32)h1 << 16);
        g_wdl[oi] = (u32)l0 | ((u32)l1 << 16);
    }
}

// ---------------- stage 1 (DCT, even/odd): two 64x128x64 GEMMs per slice ----------------
#define TSA6 144
#define TSB2 272
__global__ __launch_bounds__(256, 2)
void k_dct_mma(const float* __restrict__ xsrc) {
    extern __shared__ __align__(16) char sm[];
    const u32 OFF_BS = 36864, OFF_BD = 54272;   // total 71680
    u32 sb = smem_u32(sm);
    int tid = threadIdx.x, wid = tid >> 5, lane = tid & 31;

    int m0 = (wid >> 1) * 16, n0 = (wid & 1) * 64;
    int rowA = lane & 15;
    int kA = (lane & 16) ? 8 : 0;
    int rowK = lane & 15;
    int ntAdd = (lane & 16) ? 8 : 0;

    for (int i = tid; i < 2048; i += 256) {
        int p = i >> 9, ii = i & 511;
        int r = ii >> 3, ch = ii & 7;
        const u32* src = (p == 0) ? g_Deh : (p == 1) ? g_Del : (p == 2) ? g_Doh : g_Dol;
        cp16(sb + p*9216 + r*TSA6 + ch*16, src + r*32 + ch*4);
    }
    CP_COMMIT();
    const float* xb = xsrc + (size_t)blockIdx.x * 16384;
    for (int i = tid; i < 2048; i += 256) {
        int h = i >> 5, w4 = i & 31;
        float4 a = ((const float4*)(xb + h*128))[w4];
        float4 b = ((const float4*)(xb + (127 - h)*128))[w4];
        u32 s0 = (u32)f2h(a.x + b.x) | ((u32)f2h(a.y + b.y) << 16);
        u32 s1 = (u32)f2h(a.z + b.z) | ((u32)f2h(a.w + b.w) << 16);
        u32 d0 = (u32)f2h(a.x - b.x) | ((u32)f2h(a.y - b.y) << 16);
        u32 d1 = (u32)f2h(a.z - b.z) | ((u32)f2h(a.w - b.w) << 16);
        *(uint2*)(sm + OFF_BS + h*TSB2 + w4*8) = make_uint2(s0, s1);
        *(uint2*)(sm + OFF_BD + h*TSB2 + w4*8) = make_uint2(d0, d1);
    }
    CP_WAIT(0);
    __syncthreads();

    float accE[8][4], accO[8][4];
#pragma unroll
    for (int nt = 0; nt < 8; nt++)
#pragma unroll
        for (int q = 0; q < 4; q++) { accE[nt][q] = 0.f; accO[nt][q] = 0.f; }

#pragma unroll
    for (int ks = 0; ks < 4; ks++) {
        int k0 = ks * 16;
        u32 aeh[4], ael[4], aoh[4], aol[4];
        u32 base = (u32)((m0 + rowA) * TSA6 + (k0 + kA) * 2);
        ldsm_x4(aeh[0], aeh[1], aeh[2], aeh[3], sb + 0     + base);
        ldsm_x4(ael[0], ael[1], ael[2], ael[3], sb + 9216  + base);
        ldsm_x4(aoh[0], aoh[1], aoh[2], aoh[3], sb + 18432 + base);
        ldsm_x4(aol[0], aol[1], aol[2], aol[3], sb + 27648 + base);
        u32 rbase = (u32)((k0 + rowK) * TSB2);
#pragma unroll
        for (int nt = 0; nt < 8; nt += 2) {
            u32 off = rbase + (u32)((n0 + nt*8 + ntAdd) * 2);
            u32 bs[4], bd[4];
            ldsm_x4t(bs[0], bs[1], bs[2], bs[3], sb + OFF_BS + off);
            ldsm_x4t(bd[0], bd[1], bd[2], bd[3], sb + OFF_BD + off);
#pragma unroll
            for (int q = 0; q < 2; q++) {
                mma_f16(accE[nt + q], aeh, bs[2*q], bs[2*q + 1]);
                mma_f16(accE[nt + q], ael, bs[2*q], bs[2*q + 1]);
                mma_f16(accO[nt + q], aoh, bd[2*q], bd[2*q + 1]);
                mma_f16(accO[nt + q], aol, bd[2*q], bd[2*q + 1]);
            }
        }
    }

    u32* od = g_xd16 + (size_t)blockIdx.x * 8192;
    int r = m0 + (lane >> 2);
#pragma unroll
    for (int nt = 0; nt < 8; nt++) {
        int c2 = (n0 + nt*8)/2 + (lane & 3);
        od[(2*r)*64      + c2] = (u32)f2h(accE[nt][0]) | ((u32)f2h(accE[nt][1]) << 16);
        od[(2*r + 1)*64  + c2] = (u32)f2h(accO[nt][0]) | ((u32)f2h(accO[nt][1]) << 16);
        od[(2*r + 16)*64 + c2] = (u32)f2h(accE[nt][2]) | ((u32)f2h(accE[nt][3]) << 16);
        od[(2*r + 17)*64 + c2] = (u32)f2h(accO[nt][2]) | ((u32)f2h(accO[nt][3]) << 16);
    }
}

// ---------------- stage 4 (iDCT, even/odd): E/O butterfly, 2 slices/CTA ----------------
__global__ __launch_bounds__(256, 2)
void k_idct_mma(const float* __restrict__ bias, float* __restrict__ outp) {
    extern __shared__ __align__(16) char sm[];
    const u32 OFF_B = 36864;   // stage s: OFF_B + s*34816; even +0, odd +17408. total 106496.
    u32 sb = smem_u32(sm);
    int tid = threadIdx.x, wid = tid >> 5, lane = tid & 31;

    int m0 = (wid >> 1) * 16, n0 = (wid & 1) * 64;
    int rowA = lane & 15;
    int kA = (lane & 16) ? 8 : 0;
    int rowK = lane & 15;
    int ntAdd = (lane & 16) ? 8 : 0;

    size_t slice0 = (size_t)blockIdx.x * 2;

    auto load_b = [&](int sl, int s) {
        const u32* ys = g_y16 + (slice0 + sl) * 8192;
        u32 bBase = sb + OFF_B + s*34816;
        for (int i = tid; i < 2048; i += 256) {
            int t = i >> 10, ii = i & 1023;
            int r = ii >> 4, ch = ii & 15;
            cp16(bBase + t*17408 + r*TSB2 + ch*16, ys + (size_t)(2*r + t)*64 + ch*4);
        }
        CP_COMMIT();
    };

    for (int i = tid; i < 2048; i += 256) {
        int p = i >> 9, ii = i & 511;
        int r = ii >> 3, ch = ii & 7;
        const u32* src = (p == 0) ? g_Meh : (p == 1) ? g_Mel : (p == 2) ? g_Moh : g_Mol;
        cp16(sb + p*9216 + r*TSA6 + ch*16, src + r*32 + ch*4);
    }
    CP_COMMIT();
    load_b(0, 0);
    CP_WAIT(0);
    __syncthreads();
    load_b(1, 1);

#pragma unroll
    for (int sl = 0; sl < 2; sl++) {
        u32 bBase = sb + OFF_B + sl*34816;
        float accE[8][4], accO[8][4];
#pragma unroll
        for (int nt = 0; nt < 8; nt++)
#pragma unroll
            for (int q = 0; q < 4; q++) { accE[nt][q] = 0.f; accO[nt][q] = 0.f; }

#pragma unroll
        for (int ks = 0; ks < 4; ks++) {
            int k0 = ks * 16;
            u32 aeh[4], ael[4], aoh[4], aol[4];
            u32 base = (u32)((m0 + rowA) * TSA6 + (k0 + kA) * 2);
            ldsm_x4(aeh[0], aeh[1], aeh[2], aeh[3], sb + 0     + base);
            ldsm_x4(ael[0], ael[1], ael[2], ael[3], sb + 9216  + base);
            ldsm_x4(aoh[0], aoh[1], aoh[2], aoh[3], sb + 18432 + base);
            ldsm_x4(aol[0], aol[1], aol[2], aol[3], sb + 27648 + base);
            u32 rbase = (u32)((k0 + rowK) * TSB2);
#pragma unroll
            for (int nt = 0; nt < 8; nt += 2) {
                u32 off = rbase + (u32)((n0 + nt*8 + ntAdd) * 2);
                u32 be[4], bo[4];
                ldsm_x4t(be[0], be[1], be[2], be[3], bBase + off);
                ldsm_x4t(bo[0], bo[1], bo[2], bo[3], bBase + 17408 + off);
#pragma unroll
                for (int q = 0; q < 2; q++) {
                    mma_f16(accE[nt + q], aeh, be[2*q], be[2*q + 1]);
                    mma_f16(accE[nt + q], ael, be[2*q], be[2*q + 1]);
                    mma_f16(accO[nt + q], aoh, bo[2*q], bo[2*q + 1]);
                    mma_f16(accO[nt + q], aol, bo[2*q], bo[2*q + 1]);
                }
            }
        }

        {
            size_t o = slice0 + sl;
            float bv = bias[o & 127];
            const float is = 1.f / 256.f;
            float* op = outp + o * 16384;
            int n1 = m0 + (lane >> 2);
#pragma unroll
            for (int nt = 0; nt < 8; nt++) {
                int c = n0 + nt*8 + 2*(lane & 3);
                float e0 = accE[nt][0]*is, e1 = accE[nt][1]*is;
                float o0 = accO[nt][0]*is, o1 = accO[nt][1]*is;
                float e2 = accE[nt][2]*is, e3 = accE[nt][3]*is;
                float o2 = accO[nt][2]*is, o3 = accO[nt][3]*is;
                *(float2*)(op + n1*128 + c)         = make_float2(e0 + o0 + bv, e1 + o1 + bv);
                *(float2*)(op + (127 - n1)*128 + c) = make_float2(e0 - o0 + bv, e1 - o1 + bv);
                *(float2*)(op + (n1 + 8)*128 + c)   = make_float2(e2 + o2 + bv, e3 + o3 + bv);
                *(float2*)(op + (119 - n1)*128 + c) = make_float2(e2 - o2 + bv, e3 - o3 + bv);
            }
        }
        if (sl == 0) { CP_WAIT(0); __syncthreads(); }
    }
}

// ---------------- stage 3: per (b,k): y = (wd64 conv xd)/64; direct-store epilogue -----
#define TS3 144
__global__ __launch_bounds__(256, 2)
void k_conv_mma() {
    extern __shared__ __align__(16) char sm[];
    const u32 OFF_B = 0, OFF_A0 = 18432, OFF_A1 = 55296;   // total 92160 during load; pipeline uses all
    u32 sb = smem_u32(sm);
    int tid = threadIdx.x, wid = tid >> 5, lane = tid & 31;
    int blk = blockIdx.x, b = blk >> 7, k = blk & 127;

    for (int i = tid; i < 1024; i += 256) {
        int c = i >> 4, ch = i & 15;
        size_t gi = ((size_t)(b*64 + c)*128 + k)*64 + ch*4;
        cp16(sb + OFF_A1 + i*16, g_xd16 + gi);
    }
    CP_COMMIT();
    {
        size_t wbase = (size_t)(k*5 + 0) * 4096;
        for (int i = tid; i < 1024; i += 256) {
            int o = i >> 3, ch = i & 7;
            cp16(sb + OFF_A0 +         o*TS3 + ch*16, g_wdh + wbase + o*32 + ch*4);
            cp16(sb + OFF_A0 + 18432 + o*TS3 + ch*16, g_wdl + wbase + o*32 + ch*4);
        }
        CP_COMMIT();
    }
    CP_WAIT(1);
    __syncthreads();
    {
        const u16* sh = (const u16*)(sm + OFF_A1);
        u32* dB = (u32*)(sm + OFF_B);
        for (int i = tid; i < 4096; i += 256) {
            int w = i & 127, cp = i >> 7;
            dB[w*36 + cp] = (u32)sh[(2*cp)*128 + w] | ((u32)sh[(2*cp + 1)*128 + w] << 16);
        }
    }
    CP_WAIT(0);
    __syncthreads();

    int m0 = (wid >> 1) * 32, n0 = (wid & 1) * 64;
    int rowA = lane & 15;
    int kA = (lane & 16) ? 8 : 0;
    int rowB = lane & 7;
    int kB = (lane & 8) ? 8 : 0;
    int ntAdd = (lane & 16) ? 8 : 0;

    float acc[2][8][4];
#pragma unroll
    for (int mt = 0; mt < 2; mt++)
#pragma unroll
        for (int nt = 0; nt < 8; nt++)
#pragma unroll
            for (int q = 0; q < 4; q++) acc[mt][nt][q] = 0.f;

#pragma unroll
    for (int j = 0; j < 5; j++) {
        if (j < 4) {
            size_t wbase = (size_t)(k*5 + j + 1) * 4096;
            u32 dst = sb + (((j + 1) & 1) ? OFF_A1 : OFF_A0);
            for (int i = tid; i < 1024; i += 256) {
                int o = i >> 3, ch = i & 7;
                cp16(dst +         o*TS3 + ch*16, g_wdh + wbase + o*32 + ch*4);
                cp16(dst + 18432 + o*TS3 + ch*16, g_wdl + wbase + o*32 + ch*4);
            }
            CP_COMMIT();
        }
        u32 aBase = sb + ((j & 1) ? OFF_A1 : OFF_A0);
#pragma unroll
        for (int ks = 0; ks < 4; ks++) {
            int k0 = ks * 16;
            u32 ah[2][4], al[2][4];
#pragma unroll
            for (int mt = 0; mt < 2; mt++) {
                u32 base = (u32)((m0 + mt*16 + rowA) * TS3 + (k0 + kA) * 2);
                ldsm_x4(ah[mt][0], ah[mt][1], ah[mt][2], ah[mt][3], aBase + base);
                ldsm_x4(al[mt][0], al[mt][1], al[mt][2], al[mt][3], aBase + 18432 + base);
            }
#pragma unroll
            for (int nt = 0; nt < 8; nt += 2) {
                int wr = ((n0 + nt*8 + ntAdd + rowB) - j) & 127;
                u32 base = (u32)(wr * TS3 + (k0 + kB) * 2);
                u32 bf[4];
                ldsm_x4(bf[0], bf[1], bf[2], bf[3], sb + OFF_B + base);
#pragma unroll
                for (int q = 0; q < 2; q++)
#pragma unroll
                    for (int mt = 0; mt < 2; mt++) {
                        mma_f16(acc[mt][nt + q], ah[mt], bf[2*q], bf[2*q + 1]);
                        mma_f16(acc[mt][nt + q], al[mt], bf[2*q], bf[2*q + 1]);
                    }
            }
        }
        if (j < 4) { CP_WAIT(0); __syncthreads(); }
    }

    // epilogue: direct packed u32 stores from accumulators (no smem staging)
    const float is = 1.f / 64.f;
#pragma unroll
    for (int mt = 0; mt < 2; mt++)
#pragma unroll
        for (int nt = 0; nt < 8; nt++) {
            int o = m0 + mt*16 + (lane >> 2);
            int c2 = (n0 + nt*8)/2 + (lane & 3);
            size_t gi = ((size_t)(b*128 + o))*8192 + (size_t)k*64 + c2;
            g_y16[gi]          = (u32)f2h(acc[mt][nt][0]*is) | ((u32)f2h(acc[mt][nt][1]*is) << 16);
            g_y16[gi + 8*8192] = (u32)f2h(acc[mt][nt][2]*is) | ((u32)f2h(acc[mt][nt][3]*is) << 16);
        }
}

// ---------------- launch ----------------
extern "C" void kernel_launch(void* const* d_in, const int* in_sizes, int n_in,
                              void* d_out, int out_size) {
    const float* x    = (const float*)d_in[0];   // (8,64,128,128)
    const float* wgt  = (const float*)d_in[1];   // (128,64,5,5)
    const float* bias = (const float*)d_in[2];   // (128,)
    float* out = (float*)d_out;                  // (8,128,128,128)

    const int SMD = 71680;    // A 4x9216 + B 2x17408
    const int SMI = 106496;   // A 4x9216 + B 2x34816
    const int SM3 = 92160;    // B 18432 + A 2x36864
    cudaFuncSetAttribute(k_dct_mma,  cudaFuncAttributeMaxDynamicSharedMemorySize, SMD);
    cudaFuncSetAttribute(k_idct_mma, cudaFuncAttributeMaxDynamicSharedMemorySize, SMI);
    cudaFuncSetAttribute(k_conv_mma, cudaFuncAttributeMaxDynamicSharedMemorySize, SM3);

    k_consts  <<<32, 256>>>();
    k_wtrans  <<<640, 256>>>(wgt);
    k_dct_mma <<<BATCH*CIN,     256, SMD>>>(x);
    k_conv_mma<<<BATCH*HH,      256, SM3>>>();
    k_idct_mma<<<BATCH*COUT/2,  256, SMI>>>(bias, out);
}